// round 16
// baseline (speedup 1.0000x reference)
#include <cuda_runtime.h>
#include <cuda_fp16.h>
#include <math.h>
#include <stdint.h>

// Problem constants: B=4, L=2048, HS=2048, NH=32, HD=64, K=16, NM=128, M=B*L=8192

__device__ float g_Q[8192 * 2048];
__device__ float g_K[8192 * 2048];
__device__ float g_V[8192 * 2048];
__device__ float g_Y[8192 * 2048];
__device__ float g_LR[8192 * 32];
__device__ __half g_Hh[8192 * 2048];
__device__ __half g_Yh[8192 * 2048];
__device__ __half g_Wqh[2048 * 2048];
__device__ __half g_Wkh[2048 * 2048];
__device__ __half g_Wvh[2048 * 2048];
__device__ __half g_Woh[2048 * 2048];
__device__ __half g_Wlrh[32 * 2048];

// ---------------------------------------------------------------------------
__device__ __forceinline__ void mma_f16(float* c, const uint32_t* a, const uint32_t* b) {
    asm volatile(
        "mma.sync.aligned.m16n8k16.row.col.f32.f16.f16.f32 "
        "{%0,%1,%2,%3}, {%4,%5,%6,%7}, {%8,%9}, {%0,%1,%2,%3};"
        : "+f"(c[0]), "+f"(c[1]), "+f"(c[2]), "+f"(c[3])
        : "r"(a[0]), "r"(a[1]), "r"(a[2]), "r"(a[3]), "r"(b[0]), "r"(b[1]));
}

__device__ __forceinline__ void ldsm_x4(uint32_t* r, uint32_t addr) {
    asm volatile("ldmatrix.sync.aligned.m8n8.x4.shared.b16 {%0,%1,%2,%3}, [%4];"
                 : "=r"(r[0]), "=r"(r[1]), "=r"(r[2]), "=r"(r[3]) : "r"(addr));
}

__device__ __forceinline__ uint32_t smem_u32(const void* p) {
    uint32_t a;
    asm("{ .reg .u64 t; cvta.to.shared.u64 t, %1; cvt.u32.u64 %0, t; }" : "=r"(a) : "l"(p));
    return a;
}

__device__ __forceinline__ void cp16(uint32_t s, const void* g) {
    asm volatile("cp.async.cg.shared.global [%0], [%1], 16;" :: "r"(s), "l"(g));
}
#define CP_COMMIT() asm volatile("cp.async.commit_group;" ::: "memory")
#define CP_WAIT1()  asm volatile("cp.async.wait_group 1;" ::: "memory")

// ---------------------------------------------------------------------------
// f32 -> f16 conversion: one launch covers hidden (as 4 quarters) + 4 weights
// blockIdx.y: 0-3 -> weight w; 4-7 -> hidden quarter (y-4). lr_w separate.
// ---------------------------------------------------------------------------
__global__ void cvt_all_kernel(const float* __restrict__ hid,
                               const float* __restrict__ a, const float* __restrict__ b,
                               const float* __restrict__ c, const float* __restrict__ d,
                               __half* __restrict__ oh,
                               __half* __restrict__ oa, __half* __restrict__ ob,
                               __half* __restrict__ oc, __half* __restrict__ od)
{
    int w = blockIdx.y;
    const float* in;
    __half* out;
    if (w < 4) {
        in = (w == 0) ? a : (w == 1) ? b : (w == 2) ? c : d;
        out = (w == 0) ? oa : (w == 1) ? ob : (w == 2) ? oc : od;
    } else {
        size_t off = (size_t)(w - 4) * (2048 * 2048);
        in = hid + off;
        out = oh + off;
    }
    int i = blockIdx.x * blockDim.x + threadIdx.x;   // n8 = 2048*2048/8
    float4 v0 = ((const float4*)in)[i * 2];
    float4 v1 = ((const float4*)in)[i * 2 + 1];
    __half2* o = (__half2*)(out + (size_t)i * 8);
    o[0] = __floats2half2_rn(v0.x, v0.y);
    o[1] = __floats2half2_rn(v0.z, v0.w);
    o[2] = __floats2half2_rn(v1.x, v1.y);
    o[3] = __floats2half2_rn(v1.z, v1.w);
}

__global__ void cvt_f16_kernel(const float* __restrict__ in, __half* __restrict__ out, int n8)
{
    int i = blockIdx.x * blockDim.x + threadIdx.x;
    if (i < n8) {
        float4 v0 = ((const float4*)in)[i * 2];
        float4 v1 = ((const float4*)in)[i * 2 + 1];
        __half2* o = (__half2*)(out + (size_t)i * 8);
        o[0] = __floats2half2_rn(v0.x, v0.y);
        o[1] = __floats2half2_rn(v0.z, v0.w);
        o[2] = __floats2half2_rn(v1.x, v1.y);
        o[3] = __floats2half2_rn(v1.z, v1.w);
    }
}

// ---------------------------------------------------------------------------
// FP16 tensor-core GEMM (round-15, proven): 128x128 CTA, 8 warps 64x32, BK=32,
// 3-stage cp.async, ldmatrix frags. blockIdx.x selects (W, C) pair.
// ---------------------------------------------------------------------------
#define ST2 40
#define A_HF (128 * ST2)
#define STAGE_HF (2 * A_HF)
#define GEMM_SMEM (3 * STAGE_HF * 2)

__global__ __launch_bounds__(256, 2) void gemm_f16_nt(
    const __half* __restrict__ A,
    const __half* __restrict__ W0, const __half* __restrict__ W1_,
    const __half* __restrict__ W2_,
    float* __restrict__ C0, float* __restrict__ C1, float* __restrict__ C2)
{
    extern __shared__ __align__(16) __half smh[];

    const __half* W = (blockIdx.x == 0) ? W0 : (blockIdx.x == 1) ? W1_ : W2_;
    float* C = (blockIdx.x == 0) ? C0 : (blockIdx.x == 1) ? C1 : C2;

    int tid = threadIdx.x;
    int bm = blockIdx.z * 128, bn = blockIdx.y * 128;
    int warp = tid >> 5, lane = tid & 31;
    int gid = lane >> 2, tig = lane & 3;
    int wm = (warp & 1) * 64, wn = (warp >> 1) * 32;

    int a_row = ((lane >> 3) & 1) * 8 + (lane & 7);
    int a_col = (lane >> 4) * 8;
    int bq = lane >> 3;
    int b_rowp = (bq >> 1) * 8 + (lane & 7);
    int b_colp = (bq & 1) * 8;

    int lrow = tid >> 1, lseg = (tid & 1) * 16;
    const __half* Ag = A + (size_t)(bm + lrow) * 2048 + lseg;
    const __half* Wg = W + (size_t)(bn + lrow) * 2048 + lseg;
    uint32_t base_s = smem_u32(smh);
    uint32_t As_s = base_s + (lrow * ST2 + lseg) * 2;
    uint32_t Bs_s = base_s + (A_HF + lrow * ST2 + lseg) * 2;

    float acc[4][4][4];
#pragma unroll
    for (int mi = 0; mi < 4; mi++)
#pragma unroll
        for (int ni = 0; ni < 4; ni++)
#pragma unroll
            for (int t = 0; t < 4; t++) acc[mi][ni][t] = 0.0f;

#pragma unroll
    for (int s = 0; s < 2; s++) {
        uint32_t ao = As_s + s * STAGE_HF * 2;
        uint32_t bo = Bs_s + s * STAGE_HF * 2;
        const __half* ag = Ag + s * 32;
        const __half* wg = Wg + s * 32;
        cp16(ao, ag); cp16(ao + 16, ag + 8);
        cp16(bo, wg); cp16(bo + 16, wg + 8);
        CP_COMMIT();
    }

    const int NKT = 64;
    for (int kt = 0; kt < NKT; kt++) {
        CP_WAIT1();
        __syncthreads();

        if (kt + 2 < NKT) {
            int s = (kt + 2) % 3;
            uint32_t ao = As_s + s * STAGE_HF * 2;
            uint32_t bo = Bs_s + s * STAGE_HF * 2;
            const __half* ag = Ag + (kt + 2) * 32;
            const __half* wg = Wg + (kt + 2) * 32;
            cp16(ao, ag); cp16(ao + 16, ag + 8);
            cp16(bo, wg); cp16(bo + 16, wg + 8);
        }
        CP_COMMIT();

        uint32_t abuf = base_s + ((kt % 3) * STAGE_HF) * 2;
        uint32_t bbuf = abuf + A_HF * 2;
#pragma unroll
        for (int ks = 0; ks < 2; ks++) {
            int hb = ks * 16;
            uint32_t a[4][4], bt[2][4];
#pragma unroll
            for (int mi = 0; mi < 4; mi++)
                ldsm_x4(a[mi], abuf + ((wm + mi * 16 + a_row) * ST2 + hb + a_col) * 2);
#pragma unroll
            for (int p = 0; p < 2; p++)
                ldsm_x4(bt[p], bbuf + ((wn + p * 16 + b_rowp) * ST2 + hb + b_colp) * 2);
#pragma unroll
            for (int mi = 0; mi < 4; mi++)
#pragma unroll
                for (int ni = 0; ni < 4; ni++)
                    mma_f16(acc[mi][ni], a[mi], &bt[ni >> 1][(ni & 1) * 2]);
        }
    }

#pragma unroll
    for (int mi = 0; mi < 4; mi++) {
#pragma unroll
        for (int ni = 0; ni < 4; ni++) {
            int row0 = bm + wm + mi * 16 + gid;
            int col = bn + wn + ni * 8 + tig * 2;
            *(float2*)(C + (size_t)row0 * 2048 + col) =
                make_float2(acc[mi][ni][0], acc[mi][ni][1]);
            *(float2*)(C + (size_t)(row0 + 8) * 2048 + col) =
                make_float2(acc[mi][ni][2], acc[mi][ni][3]);
        }
    }
}

// ---------------------------------------------------------------------------
// lr projection via fp16 MMA (round-11, proven)
// ---------------------------------------------------------------------------
#define LR_A_HF (128 * 40)
#define LR_B_HF (32 * 40)
#define LR_STAGE (LR_A_HF + LR_B_HF)

__global__ __launch_bounds__(256, 1) void lr_mma_kernel(
    const __half* __restrict__ A, const __half* __restrict__ Wlr,
    const float* __restrict__ lr_bias, float* __restrict__ out)
{
    __shared__ __align__(16) __half smh[3 * LR_STAGE];

    int tid = threadIdx.x;
    int bm = blockIdx.x * 128;
    int warp = tid >> 5, lane = tid & 31;
    int gid = lane >> 2, tig = lane & 3;

    int lrow = tid >> 1, lseg = (tid & 1) * 16;
    const __half* Ag = A + (size_t)(bm + lrow) * 2048 + lseg;
    uint32_t base_s = smem_u32(smh);
    uint32_t As_s = base_s + (lrow * 40 + lseg) * 2;
    int brow = (tid & 63) >> 1, bseg2 = (tid & 1) * 16;
    const __half* Bg = Wlr + (size_t)brow * 2048 + bseg2;
    uint32_t Bs_s = base_s + (LR_A_HF + brow * 40 + bseg2) * 2;

    float acc[4][4];
#pragma unroll
    for (int ni = 0; ni < 4; ni++)
#pragma unroll
        for (int t = 0; t < 4; t++) acc[ni][t] = 0.0f;

#pragma unroll
    for (int s = 0; s < 2; s++) {
        uint32_t ao = As_s + s * LR_STAGE * 2;
        const __half* ag = Ag + s * 32;
        cp16(ao, ag); cp16(ao + 16, ag + 8);
        if (tid < 64) {
            uint32_t bo = Bs_s + s * LR_STAGE * 2;
            const __half* bg = Bg + s * 32;
            cp16(bo, bg); cp16(bo + 16, bg + 8);
        }
        CP_COMMIT();
    }

    const int NKT = 64;
    for (int kt = 0; kt < NKT; kt++) {
        CP_WAIT1();
        __syncthreads();

        if (kt + 2 < NKT) {
            int s = (kt + 2) % 3;
            uint32_t ao = As_s + s * LR_STAGE * 2;
            const __half* ag = Ag + (kt + 2) * 32;
            cp16(ao, ag); cp16(ao + 16, ag + 8);
            if (tid < 64) {
                uint32_t bo = Bs_s + s * LR_STAGE * 2;
                const __half* bg = Bg + (kt + 2) * 32;
                cp16(bo, bg); cp16(bo + 16, bg + 8);
            }
        }
        CP_COMMIT();

        const uint32_t* Aw = (const uint32_t*)(smh + (kt % 3) * LR_STAGE);
        const uint32_t* Bw = (const uint32_t*)(smh + (kt % 3) * LR_STAGE + LR_A_HF);
#pragma unroll
        for (int ks = 0; ks < 2; ks++) {
            int kb = ks * 8;
            uint32_t a[4], b[4][2];
            int m0 = warp * 16 + gid;
            a[0] = Aw[m0 * 20 + kb + tig];
            a[1] = Aw[(m0 + 8) * 20 + kb + tig];
            a[2] = Aw[m0 * 20 + kb + tig + 4];
            a[3] = Aw[(m0 + 8) * 20 + kb + tig + 4];
#pragma unroll
            for (int ni = 0; ni < 4; ni++) {
                int n0 = ni * 8 + gid;
                b[ni][0] = Bw[n0 * 20 + kb + tig];
                b[ni][1] = Bw[n0 * 20 + kb + tig + 4];
            }
#pragma unroll
            for (int ni = 0; ni < 4; ni++)
                mma_f16(acc[ni], a, b[ni]);
        }
    }

#pragma unroll
    for (int ni = 0; ni < 4; ni++) {
        int row0 = bm + warp * 16 + gid;
        int col = ni * 8 + tig * 2;
        float b0 = lr_bias[col], b1 = lr_bias[col + 1];
        *(float2*)(out + (size_t)row0 * 32 + col) =
            make_float2(acc[ni][0] + b0, acc[ni][1] + b1);
        *(float2*)(out + (size_t)(row0 + 8) * 32 + col) =
            make_float2(acc[ni][2] + b0, acc[ni][3] + b1);
    }
}

// ---------------------------------------------------------------------------
// Scan kernel, 512 threads: warp-per-row (16 warps = 16 tokens), 2 cols/thread,
// full-warp reductions. Double-buffered cp.async prefetch, 3 barriers/iter.
// ---------------------------------------------------------------------------
__device__ __forceinline__ float rsum32(float v)
{
    v += __shfl_xor_sync(0xffffffffu, v, 16);
    v += __shfl_xor_sync(0xffffffffu, v, 8);
    v += __shfl_xor_sync(0xffffffffu, v, 4);
    v += __shfl_xor_sync(0xffffffffu, v, 2);
    v += __shfl_xor_sync(0xffffffffu, v, 1);
    return v;
}

#define SSD 68
#define TILE68 (16 * SSD)
#define SCAN_SMEM (2 * 3 * TILE68 * 4)

__global__ __launch_bounds__(512, 1) void scan_kernel(
    const float* __restrict__ Q, const float* __restrict__ K_,
    const float* __restrict__ V, const float* __restrict__ LR,
    const float* __restrict__ W1_0, const float* __restrict__ b1_0,
    const float* __restrict__ lnw, const float* __restrict__ lnb,
    const float* __restrict__ ltk, float* __restrict__ Y)
{
    extern __shared__ __align__(16) float dsm[];
    __shared__ __align__(16) float W1[64 * 64];
    __shared__ __align__(16) float gr[TILE68];
    __shared__ float b1v[64], gam[64], bet[64];
    __shared__ float coef[256], evec[2][16], tok[16];

    int bh = blockIdx.x, b = bh >> 5, h = bh & 31;
    int tid = threadIdx.x;

    for (int i = tid; i < 4096; i += 512) W1[i] = W1_0[h * 4096 + i];
    if (tid < 64) {
        b1v[tid] = b1_0[h * 64 + tid];
        gam[tid] = lnw[h * 64 + tid];
        bet[tid] = lnb[h * 64 + tid];
    }
    if (tid < 16) tok[tid] = fmaxf(1.0f / (float)(tid + 1) + ltk[tid], 0.0f);

    int r = tid >> 5;             // warp = row 0..15
    int lane = tid & 31;
    int g2 = lane << 1;           // col pair 0,2,...,62

    // loader mapping: t0 covers one (row, quad); tid<256 -> Q & V, else K
    int t0 = tid & 255;
    int lk = t0 >> 4, ld4 = (t0 & 15) << 2;
    uint32_t dsm_s = smem_u32(dsm);
    size_t row_off = (size_t)lk * 2048 + ld4;
    size_t bb2048 = (size_t)b * 2048;
    uint32_t loff = (lk * SSD + ld4) * 4;

    {
        size_t gi = bb2048 * 2048 + (size_t)h * 64 + row_off;
        if (tid < 256) {
            cp16(dsm_s + loff, Q + gi);
            cp16(dsm_s + loff + 2 * TILE68 * 4, V + gi);
        } else {
            cp16(dsm_s + loff + TILE68 * 4, K_ + gi);
        }
        CP_COMMIT();
    }
    float lrx = 0.0f;
    if (tid < 16) lrx = LR[(bb2048 + tid) * 32 + h];
    __syncthreads();

    for (int nm = 0; nm < 128; nm++) {
        int buf = nm & 1;
        if (tid < 16)
            evec[buf][tid] = (1.0f / (1.0f + expf(-lrx))) * (1.0f / 64.0f);

        if (nm + 1 < 128) {
            size_t gi = (bb2048 + (size_t)(nm + 1) * 16) * 2048 + (size_t)h * 64 + row_off;
            uint32_t d0 = dsm_s + (buf ^ 1) * 3 * TILE68 * 4 + loff;
            if (tid < 256) {
                cp16(d0, Q + gi);
                cp16(d0 + 2 * TILE68 * 4, V + gi);
            } else {
                cp16(d0 + TILE68 * 4, K_ + gi);
            }
        }
        CP_COMMIT();
        CP_WAIT1();
        __syncthreads();

        if (tid < 16 && nm + 1 < 128)
            lrx = LR[(bb2048 + (size_t)(nm + 1) * 16 + tid) * 32 + h];

        const float* xq = dsm + buf * 3 * TILE68;
        const float* xk = xq + TILE68;
        const float* xv = xk + TILE68;

        // phase 1: z/qw (2 cols per thread, sequential c order per column)
        float z[2], qw[2];
        z[0] = b1v[g2]; z[1] = b1v[g2 + 1];
        qw[0] = z[0]; qw[1] = z[1];
        {
            const float4* krow = (const float4*)(xk + r * SSD);
            const float4* qrow = (const float4*)(xq + r * SSD);
            for (int c4 = 0; c4 < 16; c4++) {
                float4 k4 = krow[c4], q4 = qrow[c4];
                float kk[4] = {k4.x, k4.y, k4.z, k4.w};
                float qq[4] = {q4.x, q4.y, q4.z, q4.w};
#pragma unroll
                for (int t = 0; t < 4; t++) {
                    float2 w2 = *(const float2*)&W1[(c4 * 4 + t) * 64 + g2];
                    z[0] += kk[t] * w2.x; z[1] += kk[t] * w2.y;
                    qw[0] += qq[t] * w2.x; qw[1] += qq[t] * w2.y;
                }
            }
        }

        float s = rsum32(z[0] + z[1]);
        float mu = s * (1.0f / 64.0f);
        float xh[2]; float vs;
        xh[0] = z[0] - mu; xh[1] = z[1] - mu;
        vs = rsum32(xh[0] * xh[0] + xh[1] * xh[1]);
        float rstd = 1.0f / sqrtf(vs * (1.0f / 64.0f) + 1e-6f);
        float gxh[2]; float s1, s2;
#pragma unroll
        for (int t = 0; t < 2; t++) {
            xh[t] *= rstd;
            float tgt = xv[r * SSD + g2 + t] - xk[r * SSD + g2 + t];
            float gm = gam[g2 + t];
            gxh[t] = (gm * xh[t] + bet[g2 + t] - tgt) * gm;
        }
        s1 = rsum32(gxh[0] + gxh[1]);
        s2 = rsum32(gxh[0] * xh[0] + gxh[1] * xh[1]);
        float c1 = rstd * (1.0f / 64.0f);
        gr[r * SSD + g2]     = (64.0f * gxh[0] - s1 - xh[0] * s2) * c1;
        gr[r * SSD + g2 + 1] = (64.0f * gxh[1] - s1 - xh[1] * s2) * c1;

        // coef row i=r: lane -> (j = lane&15, half = lane>>4)
        {
            int j = lane & 15, ch = lane >> 4;
            const float4* xqv = (const float4*)(xq + r * SSD) + ch * 8;
            const float4* xkv = (const float4*)(xk + j * SSD) + ch * 8;
            float a = 0.0f;
#pragma unroll
            for (int c4 = 0; c4 < 8; c4++) {
                float4 qa = xqv[c4], kb = xkv[c4];
                a += qa.x * kb.x + qa.y * kb.y + qa.z * kb.z + qa.w * kb.w;
            }
            a += __shfl_xor_sync(0xffffffffu, a, 16);
            if (lane < 16)
                coef[r * 16 + j] = (j <= r) ? tok[r] * evec[buf][j] * (1.0f + a) : 0.0f;
        }
        __syncthreads();

        // phase 2: Z1_bar + output
        float zb[2] = {qw[0], qw[1]};
        for (int j = 0; j < 16; j++) {
            float cf = coef[r * 16 + j];
            float2 g = *(const float2*)&gr[j * SSD + g2];
            zb[0] -= cf * g.x; zb[1] -= cf * g.y;
        }
        float s0 = rsum32(zb[0] + zb[1]);
        float mu2 = s0 * (1.0f / 64.0f);
        float d0 = zb[0] - mu2, d1 = zb[1] - mu2;
        float v2 = rsum32(d0 * d0 + d1 * d1);
        float rstd2 = rsqrtf(v2 * (1.0f / 64.0f) + 1e-6f);
        {
            size_t obase = (bb2048 + (size_t)nm * 16) * 2048 + (size_t)h * 64;
            float o0 = xq[r * SSD + g2]     + gam[g2]     * (d0 * rstd2) + bet[g2];
            float o1 = xq[r * SSD + g2 + 1] + gam[g2 + 1] * (d1 * rstd2) + bet[g2 + 1];
            *(float2*)&Y[obase + (size_t)r * 2048 + g2] = make_float2(o0, o1);
        }

        // W1 update: thread handles rows r2 and r2+32, col quad g4w
        {
            int r2 = tid >> 4;            // 0..31
            int g4w = (tid & 15) << 2;
            float tok15 = tok[15];
            float4 w0 = *(float4*)&W1[r2 * 64 + g4w];
            float4 w1 = *(float4*)&W1[(r2 + 32) * 64 + g4w];
#pragma unroll
            for (int j = 0; j < 16; j++) {
                float le = tok15 * evec[buf][j];
                float4 g = *(const float4*)&gr[j * SSD + g4w];
                g.x *= le; g.y *= le; g.z *= le; g.w *= le;
                float k0 = xk[j * SSD + r2];
                float k1 = xk[j * SSD + r2 + 32];
                w0.x -= k0 * g.x; w0.y -= k0 * g.y; w0.z -= k0 * g.z; w0.w -= k0 * g.w;
                w1.x -= k1 * g.x; w1.y -= k1 * g.y; w1.z -= k1 * g.z; w1.w -= k1 * g.w;
            }
            *(float4*)&W1[r2 * 64 + g4w] = w0;
            *(float4*)&W1[(r2 + 32) * 64 + g4w] = w1;
        }
        if (tid < 64) {
            float tok15 = tok[15];
            float bb = b1v[tid];
#pragma unroll
            for (int j = 0; j < 16; j++)
                bb -= (tok15 * evec[buf][j]) * gr[j * SSD + tid];
            b1v[tid] = bb;
        }
        __syncthreads();
    }
}

// ---------------------------------------------------------------------------
// Post layernorm over HS=2048; reads fp32 Y, writes fp16 Yh for the O-GEMM.
// ---------------------------------------------------------------------------
__global__ void postln_kernel(const float* __restrict__ Y, __half* __restrict__ Yh,
                              const float* __restrict__ w, const float* __restrict__ b)
{
    int t = blockIdx.x;
    const float* row = Y + (size_t)t * 2048;
    __half* rowh = Yh + (size_t)t * 2048;
    __shared__ float rs[8], rss[8], mv[2];
    int tid = threadIdx.x;
    float v[8]; float s = 0.0f, ss = 0.0f;
#pragma unroll
    for (int i = 0; i < 8; i++) {
        v[i] = row[tid + i * 256];
        s += v[i]; ss += v[i] * v[i];
    }
#pragma unroll
    for (int m = 16; m >= 1; m >>= 1) {
        s  += __shfl_xor_sync(0xffffffffu, s, m);
        ss += __shfl_xor_sync(0xffffffffu, ss, m);
    }
    if ((tid & 31) == 0) { rs[tid >> 5] = s; rss[tid >> 5] = ss; }
    __syncthreads();
    if (tid == 0) {
        float a = 0.0f, c = 0.0f;
        for (int i = 0; i < 8; i++) { a += rs[i]; c += rss[i]; }
        float mu = a * (1.0f / 2048.0f);
        float var = c * (1.0f / 2048.0f) - mu * mu;
        mv[0] = mu; mv[1] = rsqrtf(var + 1e-6f);
    }
    __syncthreads();
    float mu = mv[0], rstd = mv[1];
#pragma unroll
    for (int i = 0; i < 8; i++) {
        int d = tid + i * 256;
        float o = w[d] * ((v[i] - mu) * rstd) + b[d];
        rowh[d] = __float2half_rn(o);
    }
}

// ---------------------------------------------------------------------------
extern "C" void kernel_launch(void* const* d_in, const int* in_sizes, int n_in,
                              void* d_out, int out_size)
{
    const float* hidden = (const float*)d_in[0];
    const float* q_w  = (const float*)d_in[2];
    const float* k_w  = (const float*)d_in[3];
    const float* v_w  = (const float*)d_in[4];
    const float* o_w  = (const float*)d_in[5];
    const float* W1_0 = (const float*)d_in[6];
    const float* b1_0 = (const float*)d_in[7];
    const float* lnw  = (const float*)d_in[8];
    const float* lnb  = (const float*)d_in[9];
    const float* lr_w = (const float*)d_in[10];
    const float* lr_b = (const float*)d_in[11];
    const float* ltk  = (const float*)d_in[12];
    const float* pnw  = (const float*)d_in[13];
    const float* pnb  = (const float*)d_in[14];
    float* out = (float*)d_out;

    float *Qp, *Kp, *Vp, *Yp, *LRp;
    __half *Hh, *Yh, *Wqh, *Wkh, *Wvh, *Woh, *Wlrh;
    cudaGetSymbolAddress((void**)&Qp,  g_Q);
    cudaGetSymbolAddress((void**)&Kp,  g_K);
    cudaGetSymbolAddress((void**)&Vp,  g_V);
    cudaGetSymbolAddress((void**)&Yp,  g_Y);
    cudaGetSymbolAddress((void**)&LRp, g_LR);
    cudaGetSymbolAddress((void**)&Hh,  g_Hh);
    cudaGetSymbolAddress((void**)&Yh,  g_Yh);
    cudaGetSymbolAddress((void**)&Wqh, g_Wqh);
    cudaGetSymbolAddress((void**)&Wkh, g_Wkh);
    cudaGetSymbolAddress((void**)&Wvh, g_Wvh);
    cudaGetSymbolAddress((void**)&Woh, g_Woh);
    cudaGetSymbolAddress((void**)&Wlrh, g_Wlrh);

    cudaFuncSetAttribute(gemm_f16_nt, cudaFuncAttributeMaxDynamicSharedMemorySize, GEMM_SMEM);
    cudaFuncSetAttribute(scan_kernel, cudaFuncAttributeMaxDynamicSharedMemorySize, SCAN_SMEM);

    dim3 gc(2048, 8);  // hidden (4 quarters) + 4 weights, one launch
    cvt_all_kernel<<<gc, 256>>>(hidden, q_w, k_w, v_w, o_w, Hh, Wqh, Wkh, Wvh, Woh);
    cvt_f16_kernel<<<32, 256>>>(lr_w, Wlrh, 32 * 2048 / 8);

    dim3 gq(3, 16, 64);   // fused Q/K/V
    gemm_f16_nt<<<gq, 256, GEMM_SMEM>>>(Hh, Wqh, Wkh, Wvh, Qp, Kp, Vp);
    lr_mma_kernel<<<64, 256>>>(Hh, Wlrh, lr_b, LRp);
    scan_kernel<<<128, 512, SCAN_SMEM>>>(Qp, Kp, Vp, LRp, W1_0, b1_0, lnw, lnb, ltk, Yp);
    postln_kernel<<<8192, 256>>>(Yp, Yh, pnw, pnb);
    dim3 go(1, 16, 64);
    gemm_f16_nt<<<go, 256, GEMM_SMEM>>>(Yh, Woh, Woh, Woh, out, out, out);
}

// round 17
// speedup vs baseline: 1.0812x; 1.0812x over previous
#include <cuda_runtime.h>
#include <cuda_fp16.h>
#include <math.h>
#include <stdint.h>

// Problem constants: B=4, L=2048, HS=2048, NH=32, HD=64, K=16, NM=128, M=B*L=8192

__device__ float g_Q[8192 * 2048];
__device__ float g_K[8192 * 2048];
__device__ float g_V[8192 * 2048];
__device__ float g_Y[8192 * 2048];
__device__ float g_LR[8192 * 32];
__device__ __half g_Hh[8192 * 2048];
__device__ __half g_Yh[8192 * 2048];
__device__ __half g_Wqh[2048 * 2048];
__device__ __half g_Wkh[2048 * 2048];
__device__ __half g_Wvh[2048 * 2048];
__device__ __half g_Woh[2048 * 2048];
__device__ __half g_Wlrh[32 * 2048];

// ---------------------------------------------------------------------------
__device__ __forceinline__ void mma_f16(float* c, const uint32_t* a, const uint32_t* b) {
    asm volatile(
        "mma.sync.aligned.m16n8k16.row.col.f32.f16.f16.f32 "
        "{%0,%1,%2,%3}, {%4,%5,%6,%7}, {%8,%9}, {%0,%1,%2,%3};"
        : "+f"(c[0]), "+f"(c[1]), "+f"(c[2]), "+f"(c[3])
        : "r"(a[0]), "r"(a[1]), "r"(a[2]), "r"(a[3]), "r"(b[0]), "r"(b[1]));
}

__device__ __forceinline__ void ldsm_x4(uint32_t* r, uint32_t addr) {
    asm volatile("ldmatrix.sync.aligned.m8n8.x4.shared.b16 {%0,%1,%2,%3}, [%4];"
                 : "=r"(r[0]), "=r"(r[1]), "=r"(r[2]), "=r"(r[3]) : "r"(addr));
}

__device__ __forceinline__ uint32_t smem_u32(const void* p) {
    uint32_t a;
    asm("{ .reg .u64 t; cvta.to.shared.u64 t, %1; cvt.u32.u64 %0, t; }" : "=r"(a) : "l"(p));
    return a;
}

__device__ __forceinline__ void cp16(uint32_t s, const void* g) {
    asm volatile("cp.async.cg.shared.global [%0], [%1], 16;" :: "r"(s), "l"(g));
}
#define CP_COMMIT() asm volatile("cp.async.commit_group;" ::: "memory")
#define CP_WAIT1()  asm volatile("cp.async.wait_group 1;" ::: "memory")

// ---------------------------------------------------------------------------
// f32 -> f16 conversion: one launch, 16 elems/thread (4 LDG.128 in flight).
// blockIdx.y: 0-3 -> weight; 4-7 -> hidden quarter.
// ---------------------------------------------------------------------------
__global__ void cvt_all_kernel(const float* __restrict__ hid,
                               const float* __restrict__ a, const float* __restrict__ b,
                               const float* __restrict__ c, const float* __restrict__ d,
                               __half* __restrict__ oh,
                               __half* __restrict__ oa, __half* __restrict__ ob,
                               __half* __restrict__ oc, __half* __restrict__ od)
{
    int w = blockIdx.y;
    const float* in;
    __half* out;
    if (w < 4) {
        in = (w == 0) ? a : (w == 1) ? b : (w == 2) ? c : d;
        out = (w == 0) ? oa : (w == 1) ? ob : (w == 2) ? oc : od;
    } else {
        size_t off = (size_t)(w - 4) * (2048 * 2048);
        in = hid + off;
        out = oh + off;
    }
    int i = blockIdx.x * blockDim.x + threadIdx.x;  // n16 = 2048*2048/16 = 262144
    const float4* ip = (const float4*)in + (size_t)i * 4;
    float4 v0 = ip[0], v1 = ip[1], v2 = ip[2], v3 = ip[3];
    __half2 h[8];
    h[0] = __floats2half2_rn(v0.x, v0.y); h[1] = __floats2half2_rn(v0.z, v0.w);
    h[2] = __floats2half2_rn(v1.x, v1.y); h[3] = __floats2half2_rn(v1.z, v1.w);
    h[4] = __floats2half2_rn(v2.x, v2.y); h[5] = __floats2half2_rn(v2.z, v2.w);
    h[6] = __floats2half2_rn(v3.x, v3.y); h[7] = __floats2half2_rn(v3.z, v3.w);
    float4* op = (float4*)(out + (size_t)i * 16);
    op[0] = *(float4*)&h[0];
    op[1] = *(float4*)&h[4];
}

__global__ void cvt_f16_kernel(const float* __restrict__ in, __half* __restrict__ out, int n8)
{
    int i = blockIdx.x * blockDim.x + threadIdx.x;
    if (i < n8) {
        float4 v0 = ((const float4*)in)[i * 2];
        float4 v1 = ((const float4*)in)[i * 2 + 1];
        __half2* o = (__half2*)(out + (size_t)i * 8);
        o[0] = __floats2half2_rn(v0.x, v0.y);
        o[1] = __floats2half2_rn(v0.z, v0.w);
        o[2] = __floats2half2_rn(v1.x, v1.y);
        o[3] = __floats2half2_rn(v1.z, v1.w);
    }
}

// ---------------------------------------------------------------------------
// FP16 tensor-core GEMM (round-15, proven): 128x128 CTA, 8 warps 64x32, BK=32,
// 3-stage cp.async, ldmatrix frags. blockIdx.x selects (W, C) pair.
// ---------------------------------------------------------------------------
#define ST2 40
#define A_HF (128 * ST2)
#define STAGE_HF (2 * A_HF)
#define GEMM_SMEM (3 * STAGE_HF * 2)

__global__ __launch_bounds__(256, 2) void gemm_f16_nt(
    const __half* __restrict__ A,
    const __half* __restrict__ W0, const __half* __restrict__ W1_,
    const __half* __restrict__ W2_,
    float* __restrict__ C0, float* __restrict__ C1, float* __restrict__ C2)
{
    extern __shared__ __align__(16) __half smh[];

    const __half* W = (blockIdx.x == 0) ? W0 : (blockIdx.x == 1) ? W1_ : W2_;
    float* C = (blockIdx.x == 0) ? C0 : (blockIdx.x == 1) ? C1 : C2;

    int tid = threadIdx.x;
    int bm = blockIdx.z * 128, bn = blockIdx.y * 128;
    int warp = tid >> 5, lane = tid & 31;
    int gid = lane >> 2, tig = lane & 3;
    int wm = (warp & 1) * 64, wn = (warp >> 1) * 32;

    int a_row = ((lane >> 3) & 1) * 8 + (lane & 7);
    int a_col = (lane >> 4) * 8;
    int bq = lane >> 3;
    int b_rowp = (bq >> 1) * 8 + (lane & 7);
    int b_colp = (bq & 1) * 8;

    int lrow = tid >> 1, lseg = (tid & 1) * 16;
    const __half* Ag = A + (size_t)(bm + lrow) * 2048 + lseg;
    const __half* Wg = W + (size_t)(bn + lrow) * 2048 + lseg;
    uint32_t base_s = smem_u32(smh);
    uint32_t As_s = base_s + (lrow * ST2 + lseg) * 2;
    uint32_t Bs_s = base_s + (A_HF + lrow * ST2 + lseg) * 2;

    float acc[4][4][4];
#pragma unroll
    for (int mi = 0; mi < 4; mi++)
#pragma unroll
        for (int ni = 0; ni < 4; ni++)
#pragma unroll
            for (int t = 0; t < 4; t++) acc[mi][ni][t] = 0.0f;

#pragma unroll
    for (int s = 0; s < 2; s++) {
        uint32_t ao = As_s + s * STAGE_HF * 2;
        uint32_t bo = Bs_s + s * STAGE_HF * 2;
        const __half* ag = Ag + s * 32;
        const __half* wg = Wg + s * 32;
        cp16(ao, ag); cp16(ao + 16, ag + 8);
        cp16(bo, wg); cp16(bo + 16, wg + 8);
        CP_COMMIT();
    }

    const int NKT = 64;
    for (int kt = 0; kt < NKT; kt++) {
        CP_WAIT1();
        __syncthreads();

        if (kt + 2 < NKT) {
            int s = (kt + 2) % 3;
            uint32_t ao = As_s + s * STAGE_HF * 2;
            uint32_t bo = Bs_s + s * STAGE_HF * 2;
            const __half* ag = Ag + (kt + 2) * 32;
            const __half* wg = Wg + (kt + 2) * 32;
            cp16(ao, ag); cp16(ao + 16, ag + 8);
            cp16(bo, wg); cp16(bo + 16, wg + 8);
        }
        CP_COMMIT();

        uint32_t abuf = base_s + ((kt % 3) * STAGE_HF) * 2;
        uint32_t bbuf = abuf + A_HF * 2;
#pragma unroll
        for (int ks = 0; ks < 2; ks++) {
            int hb = ks * 16;
            uint32_t a[4][4], bt[2][4];
#pragma unroll
            for (int mi = 0; mi < 4; mi++)
                ldsm_x4(a[mi], abuf + ((wm + mi * 16 + a_row) * ST2 + hb + a_col) * 2);
#pragma unroll
            for (int p = 0; p < 2; p++)
                ldsm_x4(bt[p], bbuf + ((wn + p * 16 + b_rowp) * ST2 + hb + b_colp) * 2);
#pragma unroll
            for (int mi = 0; mi < 4; mi++)
#pragma unroll
                for (int ni = 0; ni < 4; ni++)
                    mma_f16(acc[mi][ni], a[mi], &bt[ni >> 1][(ni & 1) * 2]);
        }
    }

#pragma unroll
    for (int mi = 0; mi < 4; mi++) {
#pragma unroll
        for (int ni = 0; ni < 4; ni++) {
            int row0 = bm + wm + mi * 16 + gid;
            int col = bn + wn + ni * 8 + tig * 2;
            *(float2*)(C + (size_t)row0 * 2048 + col) =
                make_float2(acc[mi][ni][0], acc[mi][ni][1]);
            *(float2*)(C + (size_t)(row0 + 8) * 2048 + col) =
                make_float2(acc[mi][ni][2], acc[mi][ni][3]);
        }
    }
}

// ---------------------------------------------------------------------------
// lr projection via fp16 MMA: M-tile 64 (128 CTAs for better chip fill).
// 256 threads, 4 warps of 16 rows? -> warp w handles rows w*16.. within tile:
// same structure as before but bm = blockIdx.x * 64 and 4 warps used for MMA.
// Simpler: keep 8-warp structure on 128-row tiles but grid 64 -> instead
// split M differently: keep proven kernel, grid 64, M-tile 128 (unchanged) —
// bump to 2 CTAs per M-tile via k-split would change sums. Keep proven config.
// ---------------------------------------------------------------------------
#define LR_A_HF (128 * 40)
#define LR_B_HF (32 * 40)
#define LR_STAGE (LR_A_HF + LR_B_HF)

__global__ __launch_bounds__(256, 1) void lr_mma_kernel(
    const __half* __restrict__ A, const __half* __restrict__ Wlr,
    const float* __restrict__ lr_bias, float* __restrict__ out)
{
    __shared__ __align__(16) __half smh[3 * LR_STAGE];

    int tid = threadIdx.x;
    int bm = blockIdx.x * 128;
    int warp = tid >> 5, lane = tid & 31;
    int gid = lane >> 2, tig = lane & 3;

    int lrow = tid >> 1, lseg = (tid & 1) * 16;
    const __half* Ag = A + (size_t)(bm + lrow) * 2048 + lseg;
    uint32_t base_s = smem_u32(smh);
    uint32_t As_s = base_s + (lrow * 40 + lseg) * 2;
    int brow = (tid & 63) >> 1, bseg2 = (tid & 1) * 16;
    const __half* Bg = Wlr + (size_t)brow * 2048 + bseg2;
    uint32_t Bs_s = base_s + (LR_A_HF + brow * 40 + bseg2) * 2;

    float acc[4][4];
#pragma unroll
    for (int ni = 0; ni < 4; ni++)
#pragma unroll
        for (int t = 0; t < 4; t++) acc[ni][t] = 0.0f;

#pragma unroll
    for (int s = 0; s < 2; s++) {
        uint32_t ao = As_s + s * LR_STAGE * 2;
        const __half* ag = Ag + s * 32;
        cp16(ao, ag); cp16(ao + 16, ag + 8);
        if (tid < 64) {
            uint32_t bo = Bs_s + s * LR_STAGE * 2;
            const __half* bg = Bg + s * 32;
            cp16(bo, bg); cp16(bo + 16, bg + 8);
        }
        CP_COMMIT();
    }

    const int NKT = 64;
    for (int kt = 0; kt < NKT; kt++) {
        CP_WAIT1();
        __syncthreads();

        if (kt + 2 < NKT) {
            int s = (kt + 2) % 3;
            uint32_t ao = As_s + s * LR_STAGE * 2;
            const __half* ag = Ag + (kt + 2) * 32;
            cp16(ao, ag); cp16(ao + 16, ag + 8);
            if (tid < 64) {
                uint32_t bo = Bs_s + s * LR_STAGE * 2;
                const __half* bg = Bg + (kt + 2) * 32;
                cp16(bo, bg); cp16(bo + 16, bg + 8);
            }
        }
        CP_COMMIT();

        const uint32_t* Aw = (const uint32_t*)(smh + (kt % 3) * LR_STAGE);
        const uint32_t* Bw = (const uint32_t*)(smh + (kt % 3) * LR_STAGE + LR_A_HF);
#pragma unroll
        for (int ks = 0; ks < 2; ks++) {
            int kb = ks * 8;
            uint32_t a[4], b[4][2];
            int m0 = warp * 16 + gid;
            a[0] = Aw[m0 * 20 + kb + tig];
            a[1] = Aw[(m0 + 8) * 20 + kb + tig];
            a[2] = Aw[m0 * 20 + kb + tig + 4];
            a[3] = Aw[(m0 + 8) * 20 + kb + tig + 4];
#pragma unroll
            for (int ni = 0; ni < 4; ni++) {
                int n0 = ni * 8 + gid;
                b[ni][0] = Bw[n0 * 20 + kb + tig];
                b[ni][1] = Bw[n0 * 20 + kb + tig + 4];
            }
#pragma unroll
            for (int ni = 0; ni < 4; ni++)
                mma_f16(acc[ni], a, b[ni]);
        }
    }

#pragma unroll
    for (int ni = 0; ni < 4; ni++) {
        int row0 = bm + warp * 16 + gid;
        int col = ni * 8 + tig * 2;
        float b0 = lr_bias[col], b1 = lr_bias[col + 1];
        *(float2*)(out + (size_t)row0 * 32 + col) =
            make_float2(acc[ni][0] + b0, acc[ni][1] + b1);
        *(float2*)(out + (size_t)(row0 + 8) * 32 + col) =
            make_float2(acc[ni][2] + b0, acc[ni][3] + b1);
    }
}

// ---------------------------------------------------------------------------
// Scan kernel (round-15, proven): 256 threads, one CTA per (b,h),
// double-buffered cp.async prefetch, float4 phase-1.
// ---------------------------------------------------------------------------
__device__ __forceinline__ float rsum16(float v)
{
    v += __shfl_xor_sync(0xffffffffu, v, 1);
    v += __shfl_xor_sync(0xffffffffu, v, 2);
    v += __shfl_xor_sync(0xffffffffu, v, 4);
    v += __shfl_xor_sync(0xffffffffu, v, 8);
    return v;
}

#define SSD 68
#define TILE68 (16 * SSD)
#define SCAN_SMEM (2 * 3 * TILE68 * 4)

__global__ __launch_bounds__(256, 1) void scan_kernel(
    const float* __restrict__ Q, const float* __restrict__ K_,
    const float* __restrict__ V, const float* __restrict__ LR,
    const float* __restrict__ W1_0, const float* __restrict__ b1_0,
    const float* __restrict__ lnw, const float* __restrict__ lnb,
    const float* __restrict__ ltk, float* __restrict__ Y)
{
    extern __shared__ __align__(16) float dsm[];
    __shared__ __align__(16) float W1[64 * 64];
    __shared__ __align__(16) float gr[TILE68];
    __shared__ float b1v[64], gam[64], bet[64];
    __shared__ float coef[256], evec[2][16], tok[16];

    int bh = blockIdx.x, b = bh >> 5, h = bh & 31;
    int tid = threadIdx.x;

    for (int i = tid; i < 4096; i += 256) W1[i] = W1_0[h * 4096 + i];
    if (tid < 64) {
        b1v[tid] = b1_0[h * 64 + tid];
        gam[tid] = lnw[h * 64 + tid];
        bet[tid] = lnb[h * 64 + tid];
    }
    if (tid < 16) tok[tid] = fmaxf(1.0f / (float)(tid + 1) + ltk[tid], 0.0f);

    int r = tid >> 4;
    int g4 = (tid & 15) << 2;
    int lk = tid >> 4, ld4 = (tid & 15) << 2;

    uint32_t dsm_s = smem_u32(dsm);
    size_t row_off = (size_t)lk * 2048 + ld4;
    size_t bb2048 = (size_t)b * 2048;

    {
        size_t gi = (bb2048) * 2048 + (size_t)h * 64 + row_off;
        uint32_t d0 = dsm_s + (lk * SSD + ld4) * 4;
        cp16(d0, Q + gi);
        cp16(d0 + TILE68 * 4, K_ + gi);
        cp16(d0 + 2 * TILE68 * 4, V + gi);
        CP_COMMIT();
    }
    float lrx = 0.0f;
    if (tid < 16) lrx = LR[(bb2048 + tid) * 32 + h];
    __syncthreads();

    for (int nm = 0; nm < 128; nm++) {
        int buf = nm & 1;
        if (tid < 16)
            evec[buf][tid] = (1.0f / (1.0f + expf(-lrx))) * (1.0f / 64.0f);

        if (nm + 1 < 128) {
            size_t gi = (bb2048 + (size_t)(nm + 1) * 16) * 2048 + (size_t)h * 64 + row_off;
            uint32_t d0 = dsm_s + ((buf ^ 1) * 3 * TILE68 + lk * SSD + ld4) * 4;
            cp16(d0, Q + gi);
            cp16(d0 + TILE68 * 4, K_ + gi);
            cp16(d0 + 2 * TILE68 * 4, V + gi);
        }
        CP_COMMIT();
        CP_WAIT1();
        __syncthreads();

        if (tid < 16 && nm + 1 < 128)
            lrx = LR[(bb2048 + (size_t)(nm + 1) * 16 + tid) * 32 + h];

        const float* xq = dsm + buf * 3 * TILE68;
        const float* xk = xq + TILE68;
        const float* xv = xk + TILE68;

        float z[4], qw[4];
#pragma unroll
        for (int t = 0; t < 4; t++) { z[t] = b1v[g4 + t]; qw[t] = b1v[g4 + t]; }
        {
            const float4* krow = (const float4*)(xk + r * SSD);
            const float4* qrow = (const float4*)(xq + r * SSD);
            for (int c4 = 0; c4 < 16; c4++) {
                float4 k4 = krow[c4], q4 = qrow[c4];
                float kk[4] = {k4.x, k4.y, k4.z, k4.w};
                float qq[4] = {q4.x, q4.y, q4.z, q4.w};
#pragma unroll
                for (int t = 0; t < 4; t++) {
                    float4 w4 = *(const float4*)&W1[(c4 * 4 + t) * 64 + g4];
                    z[0] += kk[t] * w4.x; z[1] += kk[t] * w4.y;
                    z[2] += kk[t] * w4.z; z[3] += kk[t] * w4.w;
                    qw[0] += qq[t] * w4.x; qw[1] += qq[t] * w4.y;
                    qw[2] += qq[t] * w4.z; qw[3] += qq[t] * w4.w;
                }
            }
        }

        float s = z[0] + z[1] + z[2] + z[3];
        s = rsum16(s);
        float mu = s * (1.0f / 64.0f);
        float xh[4]; float vs = 0.0f;
#pragma unroll
        for (int t = 0; t < 4; t++) { float d0 = z[t] - mu; xh[t] = d0; vs += d0 * d0; }
        vs = rsum16(vs);
        float rstd = 1.0f / sqrtf(vs * (1.0f / 64.0f) + 1e-6f);
        float gxh[4]; float s1 = 0.0f, s2 = 0.0f;
#pragma unroll
        for (int t = 0; t < 4; t++) {
            xh[t] *= rstd;
            float tgt = xv[r * SSD + g4 + t] - xk[r * SSD + g4 + t];
            float gm = gam[g4 + t];
            gxh[t] = (gm * xh[t] + bet[g4 + t] - tgt) * gm;
            s1 += gxh[t]; s2 += gxh[t] * xh[t];
        }
        s1 = rsum16(s1);
        s2 = rsum16(s2);
        float c1 = rstd * (1.0f / 64.0f);
#pragma unroll
        for (int t = 0; t < 4; t++)
            gr[r * SSD + g4 + t] = (64.0f * gxh[t] - s1 - xh[t] * s2) * c1;

        {
            int i = r, j = tid & 15;
            const float4* xqv = (const float4*)(xq + i * SSD);
            const float4* xkv = (const float4*)(xk + j * SSD);
            float a = 0.0f;
#pragma unroll
            for (int c4 = 0; c4 < 16; c4++) {
                float4 qa = xqv[c4], kb = xkv[c4];
                a += qa.x * kb.x + qa.y * kb.y + qa.z * kb.z + qa.w * kb.w;
            }
            coef[i * 16 + j] = (j <= i) ? tok[i] * evec[buf][j] * (1.0f + a) : 0.0f;
        }
        __syncthreads();

        float zb[4] = {qw[0], qw[1], qw[2], qw[3]};
        for (int j = 0; j < 16; j++) {
            float cf = coef[r * 16 + j];
            float4 g = *(const float4*)&gr[j * SSD + g4];
            zb[0] -= cf * g.x; zb[1] -= cf * g.y; zb[2] -= cf * g.z; zb[3] -= cf * g.w;
        }
        float s0 = zb[0] + zb[1] + zb[2] + zb[3];
        s0 = rsum16(s0);
        float mu2 = s0 * (1.0f / 64.0f);
        float v2 = 0.0f;
#pragma unroll
        for (int t = 0; t < 4; t++) { float d0 = zb[t] - mu2; v2 += d0 * d0; }
        v2 = rsum16(v2);
        float rstd2 = rsqrtf(v2 * (1.0f / 64.0f) + 1e-6f);
        {
            size_t obase = (bb2048 + (size_t)nm * 16) * 2048 + (size_t)h * 64;
            float o0 = xq[r * SSD + g4 + 0] + gam[g4 + 0] * ((zb[0] - mu2) * rstd2) + bet[g4 + 0];
            float o1 = xq[r * SSD + g4 + 1] + gam[g4 + 1] * ((zb[1] - mu2) * rstd2) + bet[g4 + 1];
            float o2 = xq[r * SSD + g4 + 2] + gam[g4 + 2] * ((zb[2] - mu2) * rstd2) + bet[g4 + 2];
            float o3 = xq[r * SSD + g4 + 3] + gam[g4 + 3] * ((zb[3] - mu2) * rstd2) + bet[g4 + 3];
            *(float4*)&Y[obase + (size_t)r * 2048 + g4] = make_float4(o0, o1, o2, o3);
        }

        {
            float tok15 = tok[15];
            float4 w0 = *(float4*)&W1[(r + 0) * 64 + g4];
            float4 w1 = *(float4*)&W1[(r + 16) * 64 + g4];
            float4 w2 = *(float4*)&W1[(r + 32) * 64 + g4];
            float4 w3 = *(float4*)&W1[(r + 48) * 64 + g4];
#pragma unroll
            for (int j = 0; j < 16; j++) {
                float le = tok15 * evec[buf][j];
                float4 g = *(const float4*)&gr[j * SSD + g4];
                g.x *= le; g.y *= le; g.z *= le; g.w *= le;
                float k0 = xk[j * SSD + r];
                float k1 = xk[j * SSD + r + 16];
                float k2 = xk[j * SSD + r + 32];
                float k3 = xk[j * SSD + r + 48];
                w0.x -= k0 * g.x; w0.y -= k0 * g.y; w0.z -= k0 * g.z; w0.w -= k0 * g.w;
                w1.x -= k1 * g.x; w1.y -= k1 * g.y; w1.z -= k1 * g.z; w1.w -= k1 * g.w;
                w2.x -= k2 * g.x; w2.y -= k2 * g.y; w2.z -= k2 * g.z; w2.w -= k2 * g.w;
                w3.x -= k3 * g.x; w3.y -= k3 * g.y; w3.z -= k3 * g.z; w3.w -= k3 * g.w;
            }
            *(float4*)&W1[(r + 0) * 64 + g4] = w0;
            *(float4*)&W1[(r + 16) * 64 + g4] = w1;
            *(float4*)&W1[(r + 32) * 64 + g4] = w2;
            *(float4*)&W1[(r + 48) * 64 + g4] = w3;
        }
        if (tid < 64) {
            float tok15 = tok[15];
            float bb = b1v[tid];
#pragma unroll
            for (int j = 0; j < 16; j++)
                bb -= (tok15 * evec[buf][j]) * gr[j * SSD + tid];
            b1v[tid] = bb;
        }
        __syncthreads();
    }
}

// ---------------------------------------------------------------------------
// Post layernorm over HS=2048; reads fp32 Y, writes fp16 Yh for the O-GEMM.
// ---------------------------------------------------------------------------
__global__ void postln_kernel(const float* __restrict__ Y, __half* __restrict__ Yh,
                              const float* __restrict__ w, const float* __restrict__ b)
{
    int t = blockIdx.x;
    const float* row = Y + (size_t)t * 2048;
    __half* rowh = Yh + (size_t)t * 2048;
    __shared__ float rs[8], rss[8], mv[2];
    int tid = threadIdx.x;
    float v[8]; float s = 0.0f, ss = 0.0f;
#pragma unroll
    for (int i = 0; i < 8; i++) {
        v[i] = row[tid + i * 256];
        s += v[i]; ss += v[i] * v[i];
    }
#pragma unroll
    for (int m = 16; m >= 1; m >>= 1) {
        s  += __shfl_xor_sync(0xffffffffu, s, m);
        ss += __shfl_xor_sync(0xffffffffu, ss, m);
    }
    if ((tid & 31) == 0) { rs[tid >> 5] = s; rss[tid >> 5] = ss; }
    __syncthreads();
    if (tid == 0) {
        float a = 0.0f, c = 0.0f;
        for (int i = 0; i < 8; i++) { a += rs[i]; c += rss[i]; }
        float mu = a * (1.0f / 2048.0f);
        float var = c * (1.0f / 2048.0f) - mu * mu;
        mv[0] = mu; mv[1] = rsqrtf(var + 1e-6f);
    }
    __syncthreads();
    float mu = mv[0], rstd = mv[1];
#pragma unroll
    for (int i = 0; i < 8; i++) {
        int d = tid + i * 256;
        float o = w[d] * ((v[i] - mu) * rstd) + b[d];
        rowh[d] = __float2half_rn(o);
    }
}

// ---------------------------------------------------------------------------
extern "C" void kernel_launch(void* const* d_in, const int* in_sizes, int n_in,
                              void* d_out, int out_size)
{
    const float* hidden = (const float*)d_in[0];
    const float* q_w  = (const float*)d_in[2];
    const float* k_w  = (const float*)d_in[3];
    const float* v_w  = (const float*)d_in[4];
    const float* o_w  = (const float*)d_in[5];
    const float* W1_0 = (const float*)d_in[6];
    const float* b1_0 = (const float*)d_in[7];
    const float* lnw  = (const float*)d_in[8];
    const float* lnb  = (const float*)d_in[9];
    const float* lr_w = (const float*)d_in[10];
    const float* lr_b = (const float*)d_in[11];
    const float* ltk  = (const float*)d_in[12];
    const float* pnw  = (const float*)d_in[13];
    const float* pnb  = (const float*)d_in[14];
    float* out = (float*)d_out;

    float *Qp, *Kp, *Vp, *Yp, *LRp;
    __half *Hh, *Yh, *Wqh, *Wkh, *Wvh, *Woh, *Wlrh;
    cudaGetSymbolAddress((void**)&Qp,  g_Q);
    cudaGetSymbolAddress((void**)&Kp,  g_K);
    cudaGetSymbolAddress((void**)&Vp,  g_V);
    cudaGetSymbolAddress((void**)&Yp,  g_Y);
    cudaGetSymbolAddress((void**)&LRp, g_LR);
    cudaGetSymbolAddress((void**)&Hh,  g_Hh);
    cudaGetSymbolAddress((void**)&Yh,  g_Yh);
    cudaGetSymbolAddress((void**)&Wqh, g_Wqh);
    cudaGetSymbolAddress((void**)&Wkh, g_Wkh);
    cudaGetSymbolAddress((void**)&Wvh, g_Wvh);
    cudaGetSymbolAddress((void**)&Woh, g_Woh);
    cudaGetSymbolAddress((void**)&Wlrh, g_Wlrh);

    cudaFuncSetAttribute(gemm_f16_nt, cudaFuncAttributeMaxDynamicSharedMemorySize, GEMM_SMEM);
    cudaFuncSetAttribute(scan_kernel, cudaFuncAttributeMaxDynamicSharedMemorySize, SCAN_SMEM);

    dim3 gc(1024, 8);  // hidden (4 quarters) + 4 weights, 16 elems/thread
    cvt_all_kernel<<<gc, 256>>>(hidden, q_w, k_w, v_w, o_w, Hh, Wqh, Wkh, Wvh, Woh);
    cvt_f16_kernel<<<32, 256>>>(lr_w, Wlrh, 32 * 2048 / 8);

    dim3 gq(3, 16, 64);   // fused Q/K/V
    gemm_f16_nt<<<gq, 256, GEMM_SMEM>>>(Hh, Wqh, Wkh, Wvh, Qp, Kp, Vp);
    lr_mma_kernel<<<64, 256>>>(Hh, Wlrh, lr_b, LRp);
    scan_kernel<<<128, 256, SCAN_SMEM>>>(Qp, Kp, Vp, LRp, W1_0, b1_0, lnw, lnb, ltk, Yp);
    postln_kernel<<<8192, 256>>>(Yp, Yh, pnw, pnb);
    dim3 go(1, 16, 64);
    gemm_f16_nt<<<go, 256, GEMM_SMEM>>>(Yh, Woh, Woh, Woh, out, out, out);
}